// round 7
// baseline (speedup 1.0000x reference)
#include <cuda_runtime.h>
#include <cstddef>

#define S_TOTAL 50000
#define T_DAYS  1024
#define JW      32
#define CHUNKS  4
#define CHUNK   (T_DAYS / CHUNKS)   // 256 days = 128 pairs = 8 x 16 unrolled
#define TPB     128

typedef unsigned long long u64;

// scratch: (SL[t], SL[t], t, t) per day; SL = inclusive prefix sum of ln r
__device__ float4 g_SLT[T_DAYS];

// ---- packed f32x2 helpers (Blackwell sm_103a) ----
__device__ __forceinline__ u64 pack2(float lo, float hi) {
    u64 r; asm("mov.b64 %0, {%1, %2};" : "=l"(r) : "f"(lo), "f"(hi)); return r;
}
__device__ __forceinline__ u64 fma2(u64 a, u64 b, u64 c) {
    u64 d; asm("fma.rn.f32x2 %0, %1, %2, %3;" : "=l"(d) : "l"(a), "l"(b), "l"(c)); return d;
}
__device__ __forceinline__ u64 mul2(u64 a, u64 b) {
    u64 d; asm("mul.rn.f32x2 %0, %1, %2;" : "=l"(d) : "l"(a), "l"(b)); return d;
}
__device__ __forceinline__ u64 add2(u64 a, u64 b) {
    u64 d; asm("add.rn.f32x2 %0, %1, %2;" : "=l"(d) : "l"(a), "l"(b)); return d;
}
// sign-flip both lanes: 2x LOP3 on the ALU pipe (fma pipe untouched)
__device__ __forceinline__ u64 neg2(u64 a) { return a ^ 0x8000000080000000ULL; }
__device__ __forceinline__ float ex2(float x) {
    float r; asm("ex2.approx.f32 %0, %1;" : "=f"(r) : "f"(x)); return r;
}
__device__ __forceinline__ u64 exp2_pk(u64 z) {
    float zl, zh;
    asm("mov.b64 {%0, %1}, %2;" : "=f"(zl), "=f"(zh) : "l"(z));
    return pack2(ex2(zl), ex2(zh));
}

// One-block prep: ln(r_t) prefix sums -> g_SLT
__global__ void prep_kernel(const float* __restrict__ r_t)
{
    __shared__ float s_part[TPB];
    const int tid = threadIdx.x;
    const int PER = T_DAYS / TPB;   // 8
    float v[PER];
    float run = 0.f;
    #pragma unroll
    for (int k = 0; k < PER; k++) { run += logf(r_t[tid * PER + k]); v[k] = run; }
    s_part[tid] = run;
    __syncthreads();
    #pragma unroll
    for (int off = 1; off < TPB; off <<= 1) {
        float add = (tid >= off) ? s_part[tid - off] : 0.f;
        __syncthreads();
        s_part[tid] += add;
        __syncthreads();
    }
    const float excl = (tid > 0) ? s_part[tid - 1] : 0.f;
    #pragma unroll
    for (int k = 0; k < PER; k++) {
        const int t = tid * PER + k;
        const float SL = excl + v[k];
        g_SLT[t] = make_float4(SL, SL, (float)t, (float)t);
    }
}

__global__ __launch_bounds__(TPB, 2)
void covid_kernel(const float* __restrict__ warmup,
                  const float* __restrict__ delta,
                  const float* __restrict__ Tser,
                  const float* __restrict__ rho,
                  const float* __restrict__ pi,
                  float* __restrict__ out)
{
    __shared__ float4 s_slt[CHUNK];    // (SL,SL,t,t) for this chunk
    __shared__ float  s_sli[JW];       // SL[t0-32+p] for ring init (chunk>0)

    const int tid   = threadIdx.x;
    const int chunk = blockIdx.y;
    const int t0    = chunk * CHUNK;

    for (int i = tid; i < CHUNK; i += TPB) s_slt[i] = g_SLT[t0 + i];
    if (chunk > 0 && tid < JW)             s_sli[tid] = g_SLT[t0 - JW + tid].x;
    __syncthreads();

    const int gid = blockIdx.x * TPB + tid;
    if (gid >= S_TOTAL / 2) return;
    const int s0 = gid * 2;

    const float LOG2E = 1.4426950408889634f;
    const float d0 = delta[s0],       d1 = delta[s0 + 1];
    const float iT0 = 1.f / Tser[s0], iT1 = 1.f / Tser[s0 + 1];
    const float rh0 = rho[s0],        rh1 = rho[s0 + 1];
    const float W0 = warmup[(JW - 1) * S_TOTAL + s0];
    const float W1 = warmup[(JW - 1) * S_TOTAL + s0 + 1];

    // z(t) = SL[t]*c1 + t*c2 + c3 ;  A_full[t+32] = exp2(z(t))
    const float c1_0 = iT0 * LOG2E,      c1_1 = iT1 * LOG2E;
    const float c2_0 = logf(d0) * LOG2E, c2_1 = logf(d1) * LOG2E;
    const float c3_0 = logf(W0) * LOG2E + c2_0;
    const float c3_1 = logf(W1) * LOG2E + c2_1;
    const u64 C1 = pack2(c1_0, c1_1);
    const u64 C2 = pack2(c2_0, c2_1);
    const u64 C3 = pack2(c3_0, c3_1);

    // FIR taps: M[t] = sum_k c[k] * x[t+k], c[k] = rho*pi[31-k], x[n]=A_full[n]
    // ce[i] = c[2i] = w[31-2i] ;  co[i] = c[2i+1] = w[30-2i] ;  cs = ce+co
    u64 ce[JW / 2], co[JW / 2], cs[JW / 2];
    #pragma unroll
    for (int i = 0; i < JW / 2; i++) {
        float2 pe = *(const float2*)&pi[(31 - 2 * i) * S_TOTAL + s0];
        float2 po_ = *(const float2*)&pi[(30 - 2 * i) * S_TOTAL + s0];
        ce[i] = pack2(pe.x * rh0, pe.y * rh1);
        co[i] = pack2(po_.x * rh0, po_.y * rh1);
        cs[i] = add2(ce[i], co[i]);
    }

    // Rings over pair index m (m0 = t0/2, multiple of 16):
    //   E[slot i] = x[t0+2i],  O[slot i] = x[t0+2i+1],  S[j] = O[j] + E[j+1]
    u64 E[16], O[16], S[16];
    if (chunk == 0) {
        #pragma unroll
        for (int q = 0; q < JW; q++) {
            float2 a = *(const float2*)&warmup[q * S_TOTAL + s0];
            u64 v = pack2(a.x, a.y);
            if (q & 1) O[q >> 1] = v; else E[q >> 1] = v;
        }
    } else {
        #pragma unroll
        for (int q = 0; q < JW; q++) {
            const float te = (float)(t0 - JW + q);
            const float sl = s_sli[q];
            const float z0 = fmaf(sl, c1_0, fmaf(te, c2_0, c3_0));
            const float z1 = fmaf(sl, c1_1, fmaf(te, c2_1, c3_1));
            u64 v = pack2(ex2(z0), ex2(z1));
            if (q & 1) O[q >> 1] = v; else E[q >> 1] = v;
        }
    }
    #pragma unroll
    for (int j = 0; j < 15; j++) S[j] = add2(O[j], E[j + 1]);
    // S[15] is stale; written first thing in iteration u=0.

    // A_cur = A(m0) = sum_i ce[i] * E[i]
    u64 A_cur = mul2(ce[0], E[0]);
    #pragma unroll
    for (int i = 1; i < 16; i++) A_cur = fma2(ce[i], E[i], A_cur);

    float* po = out + (size_t)t0 * S_TOTAL + s0;

    for (int ob = 0; ob < CHUNK / 2; ob += 16) {
        #pragma unroll
        for (int u = 0; u < 16; u++) {
            const int d = 2 * (ob + u);          // local day of M[t], t = t0+d
            // generate x[t+32] (even slot) and x[t+33] (odd slot)
            const float4 slt0 = s_slt[d];
            const float4 slt1 = s_slt[d + 1];
            const u64 z0 = fma2(pack2(slt0.x, slt0.y), C1,
                                fma2(pack2(slt0.z, slt0.w), C2, C3));
            const u64 z1 = fma2(pack2(slt1.x, slt1.y), C1,
                                fma2(pack2(slt1.z, slt1.w), C2, C3));
            const u64 Enew = exp2_pk(z0);        // E[m+16] -> slot u
            const u64 Onew = exp2_pk(z1);        // O[m+16] -> slot u (written at end)

            E[u] = Enew;                                  // slot u was dead (E[m])
            S[(u + 15) & 15] = add2(O[(u + 15) & 15], Enew);  // S[m+15]

            // A_next = sum ce[i]*E[m+1+i] ; B = sum co[i]*O[m+i] ; C = sum cs[i]*S[m+i]
            u64 An = mul2(ce[0], E[(u + 1) & 15]);
            u64 B  = mul2(co[0], O[u]);
            u64 Cc = mul2(cs[0], S[u]);
            #pragma unroll
            for (int i = 1; i < 16; i++) {
                An = fma2(ce[i], E[(u + 1 + i) & 15], An);
                B  = fma2(co[i], O[(u + i) & 15], B);
                Cc = fma2(cs[i], S[(u + i) & 15], Cc);
            }

            const u64 M0 = add2(A_cur, B);                 // M[t]
            const u64 M1 = add2(neg2(add2(An, B)), Cc);    // C - An - B = M[t+1]

            *(u64*)po = M0;
            *(u64*)(po + S_TOTAL) = M1;
            po += 2 * S_TOTAL;

            O[u] = Onew;        // after B consumed O[m] (slot u)
            A_cur = An;
        }
    }
}

extern "C" void kernel_launch(void* const* d_in, const int* in_sizes, int n_in,
                              void* d_out, int out_size)
{
    const float* r_t    = (const float*)d_in[0];
    const float* warmup = (const float*)d_in[1];
    const float* delta  = (const float*)d_in[2];
    const float* Tser   = (const float*)d_in[3];
    const float* rho    = (const float*)d_in[4];
    const float* pi     = (const float*)d_in[5];

    prep_kernel<<<1, TPB>>>(r_t);
    dim3 grid((S_TOTAL / 2 + TPB - 1) / TPB, CHUNKS);   // (196, 4)
    covid_kernel<<<grid, TPB>>>(warmup, delta, Tser, rho, pi, (float*)d_out);
}

// round 8
// speedup vs baseline: 1.0162x; 1.0162x over previous
#include <cuda_runtime.h>
#include <cstddef>

#define S_TOTAL 50000
#define T_DAYS  1024
#define JW      32
#define CHUNKS  4
#define CHUNK   (T_DAYS / CHUNKS)   // 256 days = 128 pairs = 8 x 16 unrolled
#define TPB     128

typedef unsigned long long u64;

// scratch: (SL[t], SL[t], t, t) per day; SL = inclusive prefix sum of ln r
__device__ float4 g_SLT[T_DAYS];

// ---- packed f32x2 helpers (Blackwell sm_103a) ----
__device__ __forceinline__ u64 pack2(float lo, float hi) {
    u64 r; asm("mov.b64 %0, {%1, %2};" : "=l"(r) : "f"(lo), "f"(hi)); return r;
}
__device__ __forceinline__ u64 fma2(u64 a, u64 b, u64 c) {
    u64 d; asm("fma.rn.f32x2 %0, %1, %2, %3;" : "=l"(d) : "l"(a), "l"(b), "l"(c)); return d;
}
__device__ __forceinline__ u64 mul2(u64 a, u64 b) {
    u64 d; asm("mul.rn.f32x2 %0, %1, %2;" : "=l"(d) : "l"(a), "l"(b)); return d;
}
__device__ __forceinline__ u64 add2(u64 a, u64 b) {
    u64 d; asm("add.rn.f32x2 %0, %1, %2;" : "=l"(d) : "l"(a), "l"(b)); return d;
}
// sign-flip both lanes: LOP3 on the ALU pipe (fma pipe untouched)
__device__ __forceinline__ u64 neg2(u64 a) { return a ^ 0x8000000080000000ULL; }
__device__ __forceinline__ float ex2(float x) {
    float r; asm("ex2.approx.f32 %0, %1;" : "=f"(r) : "f"(x)); return r;
}
__device__ __forceinline__ u64 exp2_pk(u64 z) {
    float zl, zh;
    asm("mov.b64 {%0, %1}, %2;" : "=f"(zl), "=f"(zh) : "l"(z));
    return pack2(ex2(zl), ex2(zh));
}

// One-block prep: ln(r_t) prefix sums -> g_SLT
__global__ void prep_kernel(const float* __restrict__ r_t)
{
    __shared__ float s_part[TPB];
    const int tid = threadIdx.x;
    const int PER = T_DAYS / TPB;   // 8
    float v[PER];
    float run = 0.f;
    #pragma unroll
    for (int k = 0; k < PER; k++) { run += logf(r_t[tid * PER + k]); v[k] = run; }
    s_part[tid] = run;
    __syncthreads();
    #pragma unroll
    for (int off = 1; off < TPB; off <<= 1) {
        float add = (tid >= off) ? s_part[tid - off] : 0.f;
        __syncthreads();
        s_part[tid] += add;
        __syncthreads();
    }
    const float excl = (tid > 0) ? s_part[tid - 1] : 0.f;
    #pragma unroll
    for (int k = 0; k < PER; k++) {
        const int t = tid * PER + k;
        const float SL = excl + v[k];
        g_SLT[t] = make_float4(SL, SL, (float)t, (float)t);
    }
}

__global__ __launch_bounds__(TPB, 2)
void covid_kernel(const float* __restrict__ warmup,
                  const float* __restrict__ delta,
                  const float* __restrict__ Tser,
                  const float* __restrict__ rho,
                  const float* __restrict__ pi,
                  float* __restrict__ out)
{
    __shared__ u64   s_SL2[CHUNK + 2]; // (SL,SL) packed for this chunk (+2 prefetch pad)
    __shared__ float s_sli[JW];        // SL[t0-32+p] for ring init (chunk>0)

    const int tid   = threadIdx.x;
    const int chunk = blockIdx.y;
    const int t0    = chunk * CHUNK;

    for (int i = tid; i < CHUNK + 2; i += TPB) {
        int tg = t0 + i; if (tg > T_DAYS - 1) tg = T_DAYS - 1;   // pad only ever discarded
        const float4 v = g_SLT[tg];
        s_SL2[i] = pack2(v.x, v.y);
    }
    if (chunk > 0 && tid < JW) s_sli[tid] = g_SLT[t0 - JW + tid].x;
    __syncthreads();

    const int gid = blockIdx.x * TPB + tid;
    if (gid >= S_TOTAL / 2) return;
    const int s0 = gid * 2;

    const float LOG2E = 1.4426950408889634f;
    const float d0 = delta[s0],       d1 = delta[s0 + 1];
    const float iT0 = 1.f / Tser[s0], iT1 = 1.f / Tser[s0 + 1];
    const float rh0 = rho[s0],        rh1 = rho[s0 + 1];
    const float W0 = warmup[(JW - 1) * S_TOTAL + s0];
    const float W1 = warmup[(JW - 1) * S_TOTAL + s0 + 1];

    // z(t) = SL[t]*c1 + t*c2 + c3 ;  A_full[t+32] = exp2(z(t))
    const float c1_0 = iT0 * LOG2E,      c1_1 = iT1 * LOG2E;
    const float c2_0 = logf(d0) * LOG2E, c2_1 = logf(d1) * LOG2E;
    const float c3_0 = logf(W0) * LOG2E + c2_0;
    const float c3_1 = logf(W1) * LOG2E + c2_1;
    const u64 C1  = pack2(c1_0, c1_1);
    const u64 C2p = pack2(c2_0, c2_1);     // +1 day increment of the t*c2 term

    // FIR taps: M[t] = sum_k c[k] * x[t+k], c[k] = rho*pi[31-k], x[n]=A_full[n]
    u64 ce[JW / 2], co[JW / 2], cs[JW / 2];
    #pragma unroll
    for (int i = 0; i < JW / 2; i++) {
        float2 pe  = *(const float2*)&pi[(31 - 2 * i) * S_TOTAL + s0];
        float2 po_ = *(const float2*)&pi[(30 - 2 * i) * S_TOTAL + s0];
        ce[i] = pack2(pe.x * rh0, pe.y * rh1);
        co[i] = pack2(po_.x * rh0, po_.y * rh1);
        cs[i] = add2(ce[i], co[i]);
    }

    // Rings over pair index m:  E[i]=x[t0+2i], O[i]=x[t0+2i+1], S[j]=O[j]+E[j+1]
    u64 E[16], O[16], S[16];
    if (chunk == 0) {
        #pragma unroll
        for (int q = 0; q < JW; q++) {
            float2 a = *(const float2*)&warmup[q * S_TOTAL + s0];
            u64 v = pack2(a.x, a.y);
            if (q & 1) O[q >> 1] = v; else E[q >> 1] = v;
        }
    } else {
        #pragma unroll
        for (int q = 0; q < JW; q++) {
            const float te = (float)(t0 - JW + q);
            const float sl = s_sli[q];
            const float z0 = fmaf(sl, c1_0, fmaf(te, c2_0, c3_0));
            const float z1 = fmaf(sl, c1_1, fmaf(te, c2_1, c3_1));
            u64 v = pack2(ex2(z0), ex2(z1));
            if (q & 1) O[q >> 1] = v; else E[q >> 1] = v;
        }
    }
    #pragma unroll
    for (int j = 0; j < 15; j++) S[j] = add2(O[j], E[j + 1]);
    // S[15] is stale; written first thing in iteration u=0.

    // A_cur = A(m0) = sum_i ce[i] * E[i]
    u64 A_cur = mul2(ce[0], E[0]);
    #pragma unroll
    for (int i = 1; i < 16; i++) A_cur = fma2(ce[i], E[i], A_cur);

    float* po = out + (size_t)t0 * S_TOTAL + s0;

    // software-pipelined SL prefetch (LDS latency hidden under MAC block)
    u64 sl_nxt0 = s_SL2[0];
    u64 sl_nxt1 = s_SL2[1];

    for (int ob = 0; ob < CHUNK / 2; ob += 16) {
        // exact resync of the incremental t*c2+c3 term (bounds drift to <=32 ulp)
        const float tg = (float)(t0 + 2 * ob);
        u64 zT = pack2(fmaf(tg, c2_0, c3_0), fmaf(tg, c2_1, c3_1));
        #pragma unroll
        for (int u = 0; u < 16; u++) {
            const int d = 2 * (ob + u);          // local day of M[t], t = t0+d
            const u64 SLa = sl_nxt0, SLb = sl_nxt1;
            sl_nxt0 = s_SL2[d + 2];              // prefetch next pair of days
            sl_nxt1 = s_SL2[d + 3];

            // z0 = SL[d]*C1 + zT ;  z1 = SL[d+1]*C1 + zT + C2 ; zT += 2*C2
            const u64 z0  = fma2(SLa, C1, zT);
            const u64 zT1 = add2(zT, C2p);
            const u64 z1  = fma2(SLb, C1, zT1);
            zT = add2(zT1, C2p);

            const u64 Enew = exp2_pk(z0);        // E[m+16] -> slot u
            const u64 Onew = exp2_pk(z1);        // O[m+16] -> slot u (written at end)

            E[u] = Enew;                                      // slot u was dead (E[m])
            S[(u + 15) & 15] = add2(O[(u + 15) & 15], Enew);  // S[m+15]

            // A_next = sum ce[i]*E[m+1+i] ; B = sum co[i]*O[m+i] ; C = sum cs[i]*S[m+i]
            u64 An = mul2(ce[0], E[(u + 1) & 15]);
            u64 B  = mul2(co[0], O[u]);
            u64 Cc = mul2(cs[0], S[u]);
            #pragma unroll
            for (int i = 1; i < 16; i++) {
                An = fma2(ce[i], E[(u + 1 + i) & 15], An);
                B  = fma2(co[i], O[(u + i) & 15], B);
                Cc = fma2(cs[i], S[(u + i) & 15], Cc);
            }

            const u64 M0 = add2(A_cur, B);                 // M[t]
            const u64 M1 = add2(neg2(add2(An, B)), Cc);    // C - An - B = M[t+1]

            *(u64*)po = M0;
            *(u64*)(po + S_TOTAL) = M1;
            po += 2 * S_TOTAL;

            O[u] = Onew;        // after B consumed O[m] (slot u)
            A_cur = An;
        }
    }
}

extern "C" void kernel_launch(void* const* d_in, const int* in_sizes, int n_in,
                              void* d_out, int out_size)
{
    const float* r_t    = (const float*)d_in[0];
    const float* warmup = (const float*)d_in[1];
    const float* delta  = (const float*)d_in[2];
    const float* Tser   = (const float*)d_in[3];
    const float* rho    = (const float*)d_in[4];
    const float* pi     = (const float*)d_in[5];

    prep_kernel<<<1, TPB>>>(r_t);
    dim3 grid((S_TOTAL / 2 + TPB - 1) / TPB, CHUNKS);   // (196, 4)
    covid_kernel<<<grid, TPB>>>(warmup, delta, Tser, rho, pi, (float*)d_out);
}